// round 1
// baseline (speedup 1.0000x reference)
#include <cuda_runtime.h>

#define TS   3584
#define DIM  1536
#define NH   12
#define HD   128
#define VS   1792
#define TPF  448
#define NW   28
#define EPS  1e-6f
#define SCALE 0.08838834764831845f   // 1/sqrt(128)

#define QB 32   // queries per attention block
#define KB 32   // keys per tile

// -------- scratch (device globals; no allocations allowed) --------
__device__ float g_q[(size_t)TS * DIM];
__device__ float g_k[(size_t)TS * DIM];
__device__ float g_v[(size_t)TS * DIM];
__device__ float g_o[(size_t)TS * DIM];

// ======================= GEMM: C = A @ W^T + bias =======================
// A: (M,K) row-major, W: (N,K) row-major, C: (M,N). M,N mult of 128, K mult of 8.
__global__ __launch_bounds__(256)
void gemm_bias_kernel(const float* __restrict__ A,
                      const float* __restrict__ W,
                      const float* __restrict__ bias,
                      float* __restrict__ C,
                      int M, int N, int K) {
    const int BM = 128, BN = 128, BK = 8, TM = 8, TN = 8;
    __shared__ float As[8][128];
    __shared__ float Ws[8][128];

    const int tid = threadIdx.x;
    const int tx  = tid & 15;    // 0..15
    const int ty  = tid >> 4;    // 0..15
    const int m0  = blockIdx.y * BM;
    const int n0  = blockIdx.x * BN;

    float acc[TM][TN];
#pragma unroll
    for (int i = 0; i < TM; i++)
#pragma unroll
        for (int j = 0; j < TN; j++) acc[i][j] = 0.f;

    const int lrow = tid >> 1;        // 0..127
    const int lcol = (tid & 1) * 4;   // 0 or 4

    for (int k0 = 0; k0 < K; k0 += BK) {
        float4 a4 = *reinterpret_cast<const float4*>(A + (size_t)(m0 + lrow) * K + k0 + lcol);
        float4 w4 = *reinterpret_cast<const float4*>(W + (size_t)(n0 + lrow) * K + k0 + lcol);
        As[lcol + 0][lrow] = a4.x; As[lcol + 1][lrow] = a4.y;
        As[lcol + 2][lrow] = a4.z; As[lcol + 3][lrow] = a4.w;
        Ws[lcol + 0][lrow] = w4.x; Ws[lcol + 1][lrow] = w4.y;
        Ws[lcol + 2][lrow] = w4.z; Ws[lcol + 3][lrow] = w4.w;
        __syncthreads();
#pragma unroll
        for (int kk = 0; kk < BK; kk++) {
            float ar[TM], wr[TN];
#pragma unroll
            for (int i = 0; i < TM; i++) ar[i] = As[kk][ty * TM + i];
#pragma unroll
            for (int j = 0; j < TN; j++) wr[j] = Ws[kk][tx * TN + j];
#pragma unroll
            for (int i = 0; i < TM; i++)
#pragma unroll
                for (int j = 0; j < TN; j++)
                    acc[i][j] += ar[i] * wr[j];
        }
        __syncthreads();
    }

#pragma unroll
    for (int i = 0; i < TM; i++) {
        int row = m0 + ty * TM + i;
#pragma unroll
        for (int j = 0; j < TN; j += 4) {
            int col = n0 + tx * TN + j;
            float4 o;
            o.x = acc[i][j + 0] + bias[col + 0];
            o.y = acc[i][j + 1] + bias[col + 1];
            o.z = acc[i][j + 2] + bias[col + 2];
            o.w = acc[i][j + 3] + bias[col + 3];
            *reinterpret_cast<float4*>(C + (size_t)row * N + col) = o;
        }
    }
}

// ======================= RMSNorm + RoPE (q and k) =======================
// grid = (TS, 2); blockDim = 256. blockIdx.y: 0 -> q, 1 -> k.
__global__ __launch_bounds__(256)
void norm_rope_kernel(float* __restrict__ q, float* __restrict__ k,
                      const float* __restrict__ freqs,
                      const float* __restrict__ nqw,
                      const float* __restrict__ nkw) {
    const int row = blockIdx.x;
    float* x = (blockIdx.y == 0 ? q : k) + (size_t)row * DIM;
    const float* w = (blockIdx.y == 0) ? nqw : nkw;
    const int tid = threadIdx.x;

    float ss = 0.f;
    for (int i = tid; i < DIM; i += 256) { float v = x[i]; ss += v * v; }
#pragma unroll
    for (int o = 16; o > 0; o >>= 1) ss += __shfl_xor_sync(~0u, ss, o);
    __shared__ float warpsum[8];
    if ((tid & 31) == 0) warpsum[tid >> 5] = ss;
    __syncthreads();
    float tot = 0.f;
#pragma unroll
    for (int i = 0; i < 8; i++) tot += warpsum[i];
    const float rs = rsqrtf(tot / (float)DIM + EPS);

    // position within view
    const int tv = row % VS;
    const int f  = tv / TPF;
    const int r  = tv % TPF;
    const int hh = r / NW;
    const int ww = r % NW;

    for (int p = tid; p < DIM / 2; p += 256) {
        int c = p & 63;  // channel within head (HD/2 = 64)
        int idx = (c < 22) ? f : ((c < 43) ? hh : ww);
        float ang = freqs[idx * 64 + c];
        float sn, cs;
        sincosf(ang, &sn, &cs);
        float x0 = x[2 * p]     * rs * w[2 * p];
        float x1 = x[2 * p + 1] * rs * w[2 * p + 1];
        x[2 * p]     = x0 * cs - x1 * sn;
        x[2 * p + 1] = x0 * sn + x1 * cs;
    }
}

// ======================= Fused flash attention =======================
// Single softmax over union keyset: same-view 1792 keys + other-view same-frame
// 448 keys (disjoint) == lse-fusion of the two reference attentions.
// grid = (TS/QB, NH), block = 256 (8 warps, 4 queries per warp).
__global__ __launch_bounds__(256)
void attn_kernel(const float* __restrict__ Q,
                 const float* __restrict__ K,
                 const float* __restrict__ Vv,
                 float* __restrict__ O) {
    extern __shared__ float sm[];
    const int KROW = HD + 4;  // 132: conflict-free padded stride for K/V tiles
    float* Qs = sm;                        // QB*HD       = 4096 floats
    float* Ks = Qs + QB * HD;              // KB*KROW     = 4224 floats
    float* Vs = Ks + KB * KROW;            // KB*KROW     = 4224 floats
    float* Ps = Vs + KB * KROW;            // 8*KB*4      = 1024 floats

    const int head = blockIdx.y;
    const int q0   = blockIdx.x * QB;
    const int v    = q0 / VS;
    const int f    = (q0 % VS) / TPF;
    const int tid  = threadIdx.x;
    const int warp = tid >> 5;
    const int lane = tid & 31;

    // load Q tile (32 rows x 128 dims of this head)
    for (int i = tid; i < QB * HD / 4; i += 256) {
        int qr = i >> 5;
        int d4 = (i & 31) << 2;
        *(float4*)&Qs[qr * HD + d4] =
            *(const float4*)&Q[(size_t)(q0 + qr) * DIM + head * HD + d4];
    }

    float m[4], l[4];
    float4 acc[4];
#pragma unroll
    for (int i = 0; i < 4; i++) {
        m[i] = -1e30f; l[i] = 0.f;
        acc[i] = make_float4(0.f, 0.f, 0.f, 0.f);
    }

    const int baseA = v * VS;                    // same-view keys [0,1792)
    const int baseB = (1 - v) * VS + f * TPF;    // other view, same frame [0,448)
    const int NTILE_A = VS / KB;                 // 56
    const int NTILES  = (VS + TPF) / KB;         // 70

    for (int tile = 0; tile < NTILES; tile++) {
        const int kbase = (tile < NTILE_A) ? (baseA + tile * KB)
                                           : (baseB + (tile - NTILE_A) * KB);
        __syncthreads();  // previous tile fully consumed
        for (int i = tid; i < KB * HD / 4; i += 256) {
            int kr = i >> 5;
            int d4 = (i & 31) << 2;
            *(float4*)&Ks[kr * KROW + d4] =
                *(const float4*)&K[(size_t)(kbase + kr) * DIM + head * HD + d4];
            *(float4*)&Vs[kr * KROW + d4] =
                *(const float4*)&Vv[(size_t)(kbase + kr) * DIM + head * HD + d4];
        }
        __syncthreads();

        // ---- QK: lane owns key = lane; 4 queries per warp ----
        float s0 = 0.f, s1 = 0.f, s2 = 0.f, s3 = 0.f;
#pragma unroll
        for (int d4 = 0; d4 < HD; d4 += 4) {
            float4 kv = *(const float4*)&Ks[lane * KROW + d4];
            float4 qa = *(const float4*)&Qs[(warp * 4 + 0) * HD + d4];
            float4 qb = *(const float4*)&Qs[(warp * 4 + 1) * HD + d4];
            float4 qc = *(const float4*)&Qs[(warp * 4 + 2) * HD + d4];
            float4 qd = *(const float4*)&Qs[(warp * 4 + 3) * HD + d4];
            s0 += qa.x * kv.x + qa.y * kv.y + qa.z * kv.z + qa.w * kv.w;
            s1 += qb.x * kv.x + qb.y * kv.y + qb.z * kv.z + qb.w * kv.w;
            s2 += qc.x * kv.x + qc.y * kv.y + qc.z * kv.z + qc.w * kv.w;
            s3 += qd.x * kv.x + qd.y * kv.y + qd.z * kv.z + qd.w * kv.w;
        }
        float sq[4] = {s0, s1, s2, s3};
        float pv[4];
#pragma unroll
        for (int qq = 0; qq < 4; qq++) {
            float sv = sq[qq] * SCALE;
            float tm = sv;
#pragma unroll
            for (int o = 16; o > 0; o >>= 1)
                tm = fmaxf(tm, __shfl_xor_sync(~0u, tm, o));
            float mn   = fmaxf(m[qq], tm);
            float corr = __expf(m[qq] - mn);
            float p    = __expf(sv - mn);
            m[qq] = mn;
            float ps = p;
#pragma unroll
            for (int o = 16; o > 0; o >>= 1) ps += __shfl_xor_sync(~0u, ps, o);
            l[qq] = l[qq] * corr + ps;
            acc[qq].x *= corr; acc[qq].y *= corr;
            acc[qq].z *= corr; acc[qq].w *= corr;
            pv[qq] = p;
        }
        *(float4*)&Ps[(warp * KB + lane) * 4] = make_float4(pv[0], pv[1], pv[2], pv[3]);
        __syncwarp();

        // ---- PV: lane owns dims [4*lane, 4*lane+4) ----
#pragma unroll
        for (int j = 0; j < KB; j++) {
            float4 vv = *(const float4*)&Vs[j * KROW + lane * 4];
            float4 pj = *(const float4*)&Ps[(warp * KB + j) * 4];
            acc[0].x += pj.x * vv.x; acc[0].y += pj.x * vv.y;
            acc[0].z += pj.x * vv.z; acc[0].w += pj.x * vv.w;
            acc[1].x += pj.y * vv.x; acc[1].y += pj.y * vv.y;
            acc[1].z += pj.y * vv.z; acc[1].w += pj.y * vv.w;
            acc[2].x += pj.z * vv.x; acc[2].y += pj.z * vv.y;
            acc[2].z += pj.z * vv.z; acc[2].w += pj.z * vv.w;
            acc[3].x += pj.w * vv.x; acc[3].y += pj.w * vv.y;
            acc[3].z += pj.w * vv.z; acc[3].w += pj.w * vv.w;
        }
    }

#pragma unroll
    for (int qq = 0; qq < 4; qq++) {
        float inv = 1.f / l[qq];
        int row = q0 + warp * 4 + qq;
        float4 o = make_float4(acc[qq].x * inv, acc[qq].y * inv,
                               acc[qq].z * inv, acc[qq].w * inv);
        *(float4*)&O[(size_t)row * DIM + head * HD + lane * 4] = o;
    }
}

// ======================= launch =======================
extern "C" void kernel_launch(void* const* d_in, const int* in_sizes, int n_in,
                              void* d_out, int out_size) {
    const float* x     = (const float*)d_in[0];
    const float* freqs = (const float*)d_in[1];
    const float* q_w   = (const float*)d_in[2];
    const float* q_b   = (const float*)d_in[3];
    const float* k_w   = (const float*)d_in[4];
    const float* k_b   = (const float*)d_in[5];
    const float* v_w   = (const float*)d_in[6];
    const float* v_b   = (const float*)d_in[7];
    const float* o_w   = (const float*)d_in[8];
    const float* o_b   = (const float*)d_in[9];
    const float* nqw   = (const float*)d_in[10];
    const float* nkw   = (const float*)d_in[11];

    float *gq, *gk, *gv, *go;
    cudaGetSymbolAddress((void**)&gq, g_q);
    cudaGetSymbolAddress((void**)&gk, g_k);
    cudaGetSymbolAddress((void**)&gv, g_v);
    cudaGetSymbolAddress((void**)&go, g_o);

    dim3 gemm_grid(DIM / 128, TS / 128);
    gemm_bias_kernel<<<gemm_grid, 256>>>(x, q_w, q_b, gq, TS, DIM, DIM);
    gemm_bias_kernel<<<gemm_grid, 256>>>(x, k_w, k_b, gk, TS, DIM, DIM);
    gemm_bias_kernel<<<gemm_grid, 256>>>(x, v_w, v_b, gv, TS, DIM, DIM);

    norm_rope_kernel<<<dim3(TS, 2), 256>>>(gq, gk, freqs, nqw, nkw);

    const int KROW = HD + 4;
    size_t smem = (size_t)(QB * HD + 2 * KB * KROW + 8 * KB * 4) * sizeof(float);
    cudaFuncSetAttribute(attn_kernel, cudaFuncAttributeMaxDynamicSharedMemorySize,
                         (int)smem);
    attn_kernel<<<dim3(TS / QB, NH), 256, smem>>>(gq, gk, gv, go);

    gemm_bias_kernel<<<gemm_grid, 256>>>(go, o_w, o_b, (float*)d_out, TS, DIM, DIM);
}

// round 3
// speedup vs baseline: 1.4562x; 1.4562x over previous
#include <cuda_runtime.h>
#include <cuda_bf16.h>
#include <cstdint>

#define TS   3584
#define DIM  1536
#define NH   12
#define HD   128
#define VS   1792
#define TPF  448
#define NW   28
#define EPS  1e-6f
#define SCALE 0.08838834764831845f   // 1/sqrt(128)

#define QB 32
#define KB 32

// -------- scratch (device globals; no allocations allowed) --------
__device__ float g_q[(size_t)TS * DIM];
__device__ float g_k[(size_t)TS * DIM];
__device__ float g_v[(size_t)TS * DIM];
__device__ __nv_bfloat16 g_xh[(size_t)TS * DIM];
__device__ __nv_bfloat16 g_xl[(size_t)TS * DIM];
__device__ __nv_bfloat16 g_oh[(size_t)TS * DIM];
__device__ __nv_bfloat16 g_ol[(size_t)TS * DIM];
__device__ __nv_bfloat16 g_wh[4][(size_t)DIM * DIM];
__device__ __nv_bfloat16 g_wl[4][(size_t)DIM * DIM];

// ======================= mma.sync helpers =======================
__device__ __forceinline__ uint32_t s2u(const void* p) {
    uint32_t a;
    asm("{ .reg .u64 t; cvta.to.shared.u64 t, %1; cvt.u32.u64 %0, t; }"
        : "=r"(a) : "l"(p));
    return a;
}

__device__ __forceinline__ void ldsm_x4(uint32_t* r, uint32_t addr) {
    asm volatile("ldmatrix.sync.aligned.m8n8.x4.shared.b16 {%0,%1,%2,%3}, [%4];"
                 : "=r"(r[0]), "=r"(r[1]), "=r"(r[2]), "=r"(r[3]) : "r"(addr));
}
__device__ __forceinline__ void ldsm_x2(uint32_t* r, uint32_t addr) {
    asm volatile("ldmatrix.sync.aligned.m8n8.x2.shared.b16 {%0,%1}, [%2];"
                 : "=r"(r[0]), "=r"(r[1]) : "r"(addr));
}
__device__ __forceinline__ void mma16816(float* c, const uint32_t* a, const uint32_t* b) {
    asm volatile(
        "mma.sync.aligned.m16n8k16.row.col.f32.bf16.bf16.f32 "
        "{%0,%1,%2,%3}, {%4,%5,%6,%7}, {%8,%9}, {%0,%1,%2,%3};"
        : "+f"(c[0]), "+f"(c[1]), "+f"(c[2]), "+f"(c[3])
        : "r"(a[0]), "r"(a[1]), "r"(a[2]), "r"(a[3]), "r"(b[0]), "r"(b[1]));
}

// ======================= fp32 -> (hi, lo) bf16 split =======================
__global__ __launch_bounds__(256)
void split_kernel(const float* __restrict__ in,
                  __nv_bfloat16* __restrict__ hi,
                  __nv_bfloat16* __restrict__ lo, int n4) {
    int i = blockIdx.x * 256 + threadIdx.x;
    if (i >= n4) return;
    float4 v = ((const float4*)in)[i];
    __nv_bfloat16 h0 = __float2bfloat16(v.x);
    __nv_bfloat16 h1 = __float2bfloat16(v.y);
    __nv_bfloat16 h2 = __float2bfloat16(v.z);
    __nv_bfloat16 h3 = __float2bfloat16(v.w);
    __nv_bfloat162 H0, H1, L0, L1;
    H0.x = h0; H0.y = h1; H1.x = h2; H1.y = h3;
    L0.x = __float2bfloat16(v.x - __bfloat162float(h0));
    L0.y = __float2bfloat16(v.y - __bfloat162float(h1));
    L1.x = __float2bfloat16(v.z - __bfloat162float(h2));
    L1.y = __float2bfloat16(v.w - __bfloat162float(h3));
    ((__nv_bfloat162*)hi)[2 * i]     = H0;
    ((__nv_bfloat162*)hi)[2 * i + 1] = H1;
    ((__nv_bfloat162*)lo)[2 * i]     = L0;
    ((__nv_bfloat162*)lo)[2 * i + 1] = L1;
}

// ======================= mma.sync split-bf16 GEMM =======================
// C[m,n] = sum_k A[m,k]*W[n,k] + bias[n]  via Ah*Wh + Ah*Wl + Al*Wh.
// CTA tile 128x128, K chunks of 32, double-buffered smem.
#define SSTR 40                 // bf16 elems per smem row (80 B, ldmatrix conflict-free)
#define TILE_E (128 * SSTR)     // 5120 elems per tile
#define BUF_E  (4 * TILE_E)     // Ah, Al, Wh, Wl
#define GEMM_SMEM_BYTES (2 * BUF_E * 2)

__global__ __launch_bounds__(256)
void gemm_mma(const __nv_bfloat16* __restrict__ Ah, const __nv_bfloat16* __restrict__ Al,
              const __nv_bfloat16* __restrict__ Wh, const __nv_bfloat16* __restrict__ Wl,
              const float* __restrict__ bias, float* __restrict__ C,
              int M, int N, int K) {
    extern __shared__ __nv_bfloat16 sm[];
    const int tid  = threadIdx.x;
    const int warp = tid >> 5, lane = tid & 31;
    const int wm   = warp & 1;          // 2 M-blocks of 64
    const int wn   = warp >> 1;         // 4 N-blocks of 32
    const int m0   = blockIdx.y * 128, n0 = blockIdx.x * 128;
    const uint32_t sbase = s2u(sm);

    float acc[4][4][4];
#pragma unroll
    for (int i = 0; i < 4; i++)
#pragma unroll
        for (int j = 0; j < 4; j++)
#pragma unroll
            for (int k = 0; k < 4; k++) acc[i][j][k] = 0.f;

    const __nv_bfloat16* srcs[4] = {Ah, Al, Wh, Wl};

    auto load_chunk = [&](int k0, int b) {
        __nv_bfloat16* base = sm + b * BUF_E;
#pragma unroll
        for (int t = 0; t < 4; t++) {
            const __nv_bfloat16* src = srcs[t] + (size_t)(t < 2 ? m0 : n0) * K + k0;
            __nv_bfloat16* dst = base + t * TILE_E;
#pragma unroll
            for (int j = 0; j < 2; j++) {
                int idx = tid + j * 256;      // 0..511
                int row = idx >> 2, seg = idx & 3;
                *(uint4*)(dst + row * SSTR + seg * 8) =
                    *(const uint4*)(src + (size_t)row * K + seg * 8);
            }
        }
    };

    const int NC = K / 32;
    load_chunk(0, 0);
    __syncthreads();

    for (int c = 0; c < NC; c++) {
        const int b = c & 1;
        const uint32_t bb = sbase + b * (BUF_E * 2);
#pragma unroll
        for (int ks = 0; ks < 2; ks++) {
            uint32_t af[4][4], bf[4][2];
            // A-fragment smem offset (bytes): tile + (row)*80 + ks*32 + (lane>>4)*16
            const uint32_t arow = (uint32_t)(wm * 64 + (lane & 15));
            const uint32_t aoff = arow * (SSTR * 2) + ks * 32 + (lane >> 4) * 16;
            const uint32_t brow = (uint32_t)(wn * 32 + (lane & 7));
            const uint32_t boff = brow * (SSTR * 2) + ks * 32 + ((lane >> 3) & 1) * 16;

            // ---- term 1: Ah * Wh ----
#pragma unroll
            for (int mt = 0; mt < 4; mt++)
                ldsm_x4(af[mt], bb + 0 * (TILE_E * 2) + aoff + mt * 16 * (SSTR * 2));
#pragma unroll
            for (int nt = 0; nt < 4; nt++)
                ldsm_x2(bf[nt], bb + 2 * (TILE_E * 2) + boff + nt * 8 * (SSTR * 2));
#pragma unroll
            for (int mt = 0; mt < 4; mt++)
#pragma unroll
                for (int nt = 0; nt < 4; nt++)
                    mma16816(acc[mt][nt], af[mt], bf[nt]);

            // ---- term 2: Al * Wh (reuse B frags) ----
#pragma unroll
            for (int mt = 0; mt < 4; mt++)
                ldsm_x4(af[mt], bb + 1 * (TILE_E * 2) + aoff + mt * 16 * (SSTR * 2));
#pragma unroll
            for (int mt = 0; mt < 4; mt++)
#pragma unroll
                for (int nt = 0; nt < 4; nt++)
                    mma16816(acc[mt][nt], af[mt], bf[nt]);

            // ---- term 3: Ah * Wl ----
#pragma unroll
            for (int mt = 0; mt < 4; mt++)
                ldsm_x4(af[mt], bb + 0 * (TILE_E * 2) + aoff + mt * 16 * (SSTR * 2));
#pragma unroll
            for (int nt = 0; nt < 4; nt++)
                ldsm_x2(bf[nt], bb + 3 * (TILE_E * 2) + boff + nt * 8 * (SSTR * 2));
#pragma unroll
            for (int mt = 0; mt < 4; mt++)
#pragma unroll
                for (int nt = 0; nt < 4; nt++)
                    mma16816(acc[mt][nt], af[mt], bf[nt]);
        }
        if (c + 1 < NC) load_chunk((c + 1) * 32, b ^ 1);
        __syncthreads();
    }

    // ---- epilogue: regs + bias -> gmem ----
    const int row_base = m0 + wm * 64 + (lane >> 2);
    const int col_base = n0 + wn * 32 + (lane & 3) * 2;
#pragma unroll
    for (int mt = 0; mt < 4; mt++) {
#pragma unroll
        for (int nt = 0; nt < 4; nt++) {
            int r = row_base + mt * 16;
            int cc = col_base + nt * 8;
            float bx = bias[cc], by = bias[cc + 1];
            float2 o0 = make_float2(acc[mt][nt][0] + bx, acc[mt][nt][1] + by);
            float2 o1 = make_float2(acc[mt][nt][2] + bx, acc[mt][nt][3] + by);
            *(float2*)(C + (size_t)r * N + cc)       = o0;
            *(float2*)(C + (size_t)(r + 8) * N + cc) = o1;
        }
    }
}

// ======================= RMSNorm + RoPE (q and k) =======================
__global__ __launch_bounds__(256)
void norm_rope_kernel(float* __restrict__ q, float* __restrict__ k,
                      const float* __restrict__ freqs,
                      const float* __restrict__ nqw,
                      const float* __restrict__ nkw) {
    const int row = blockIdx.x;
    float* x = (blockIdx.y == 0 ? q : k) + (size_t)row * DIM;
    const float* w = (blockIdx.y == 0) ? nqw : nkw;
    const int tid = threadIdx.x;

    float ss = 0.f;
    for (int i = tid; i < DIM; i += 256) { float v = x[i]; ss += v * v; }
#pragma unroll
    for (int o = 16; o > 0; o >>= 1) ss += __shfl_xor_sync(~0u, ss, o);
    __shared__ float warpsum[8];
    if ((tid & 31) == 0) warpsum[tid >> 5] = ss;
    __syncthreads();
    float tot = 0.f;
#pragma unroll
    for (int i = 0; i < 8; i++) tot += warpsum[i];
    const float rs = rsqrtf(tot / (float)DIM + EPS);

    const int tv = row % VS;
    const int f  = tv / TPF;
    const int r  = tv % TPF;
    const int hh = r / NW;
    const int ww = r % NW;

    for (int p = tid; p < DIM / 2; p += 256) {
        int c = p & 63;
        int idx = (c < 22) ? f : ((c < 43) ? hh : ww);
        float ang = freqs[idx * 64 + c];
        float sn, cs;
        sincosf(ang, &sn, &cs);
        float x0 = x[2 * p]     * rs * w[2 * p];
        float x1 = x[2 * p + 1] * rs * w[2 * p + 1];
        x[2 * p]     = x0 * cs - x1 * sn;
        x[2 * p + 1] = x0 * sn + x1 * cs;
    }
}

// ======================= Fused flash attention =======================
// Single softmax over union keyset (same-view 1792 + other-view same-frame 448).
// Writes output as split bf16 (hi, lo) for the tensor-core O-projection.
__global__ __launch_bounds__(256)
void attn_kernel(const float* __restrict__ Q,
                 const float* __restrict__ K,
                 const float* __restrict__ Vv,
                 __nv_bfloat16* __restrict__ Oh,
                 __nv_bfloat16* __restrict__ Ol) {
    extern __shared__ float smf[];
    const int KROW = HD + 4;
    float* Qs = smf;
    float* Ks = Qs + QB * HD;
    float* Vs = Ks + KB * KROW;
    float* Ps = Vs + KB * KROW;

    const int head = blockIdx.y;
    const int q0   = blockIdx.x * QB;
    const int v    = q0 / VS;
    const int f    = (q0 % VS) / TPF;
    const int tid  = threadIdx.x;
    const int warp = tid >> 5;
    const int lane = tid & 31;

    for (int i = tid; i < QB * HD / 4; i += 256) {
        int qr = i >> 5;
        int d4 = (i & 31) << 2;
        *(float4*)&Qs[qr * HD + d4] =
            *(const float4*)&Q[(size_t)(q0 + qr) * DIM + head * HD + d4];
    }

    float m[4], l[4];
    float4 acc[4];
#pragma unroll
    for (int i = 0; i < 4; i++) {
        m[i] = -1e30f; l[i] = 0.f;
        acc[i] = make_float4(0.f, 0.f, 0.f, 0.f);
    }

    const int baseA = v * VS;
    const int baseB = (1 - v) * VS + f * TPF;
    const int NTILE_A = VS / KB;
    const int NTILES  = (VS + TPF) / KB;

    for (int tile = 0; tile < NTILES; tile++) {
        const int kbase = (tile < NTILE_A) ? (baseA + tile * KB)
                                           : (baseB + (tile - NTILE_A) * KB);
        __syncthreads();
        for (int i = tid; i < KB * HD / 4; i += 256) {
            int kr = i >> 5;
            int d4 = (i & 31) << 2;
            *(float4*)&Ks[kr * KROW + d4] =
                *(const float4*)&K[(size_t)(kbase + kr) * DIM + head * HD + d4];
            *(float4*)&Vs[kr * KROW + d4] =
                *(const float4*)&Vv[(size_t)(kbase + kr) * DIM + head * HD + d4];
        }
        __syncthreads();

        float s0 = 0.f, s1 = 0.f, s2 = 0.f, s3 = 0.f;
#pragma unroll
        for (int d4 = 0; d4 < HD; d4 += 4) {
            float4 kv = *(const float4*)&Ks[lane * KROW + d4];
            float4 qa = *(const float4*)&Qs[(warp * 4 + 0) * HD + d4];
            float4 qb = *(const float4*)&Qs[(warp * 4 + 1) * HD + d4];
            float4 qc = *(const float4*)&Qs[(warp * 4 + 2) * HD + d4];
            float4 qd = *(const float4*)&Qs[(warp * 4 + 3) * HD + d4];
            s0 += qa.x * kv.x + qa.y * kv.y + qa.z * kv.z + qa.w * kv.w;
            s1 += qb.x * kv.x + qb.y * kv.y + qb.z * kv.z + qb.w * kv.w;
            s2 += qc.x * kv.x + qc.y * kv.y + qc.z * kv.z + qc.w * kv.w;
            s3 += qd.x * kv.x + qd.y * kv.y + qd.z * kv.z + qd.w * kv.w;
        }
        float sq[4] = {s0, s1, s2, s3};
        float pv[4];
#pragma unroll
        for (int qq = 0; qq < 4; qq++) {
            float sv = sq[qq] * SCALE;
            float tm = sv;
#pragma unroll
            for (int o = 16; o > 0; o >>= 1)
                tm = fmaxf(tm, __shfl_xor_sync(~0u, tm, o));
            float mn   = fmaxf(m[qq], tm);
            float corr = __expf(m[qq] - mn);
            float p    = __expf(sv - mn);
            m[qq] = mn;
            float ps = p;
#pragma unroll
            for (int o = 16; o > 0; o >>= 1) ps += __shfl_xor_sync(~0u, ps, o);
            l[qq] = l[qq] * corr + ps;
            acc[qq].x *= corr; acc[qq].y *= corr;
            acc[qq].z *= corr; acc[qq].w *= corr;
            pv[qq] = p;
        }
        *(float4*)&Ps[(warp * KB + lane) * 4] = make_float4(pv[0], pv[1], pv[2], pv[3]);
        __syncwarp();

#pragma unroll
        for (int j = 0; j < KB; j++) {
            float4 vv = *(const float4*)&Vs[j * KROW + lane * 4];
            float4 pj = *(const float4*)&Ps[(warp * KB + j) * 4];
            acc[0].x += pj.x * vv.x; acc[0].y += pj.x * vv.y;
            acc[0].z += pj.x * vv.z; acc[0].w += pj.x * vv.w;
            acc[1].x += pj.y * vv.x; acc[1].y += pj.y * vv.y;
            acc[1].z += pj.y * vv.z; acc[1].w += pj.y * vv.w;
            acc[2].x += pj.z * vv.x; acc[2].y += pj.z * vv.y;
            acc[2].z += pj.z * vv.z; acc[2].w += pj.z * vv.w;
            acc[3].x += pj.w * vv.x; acc[3].y += pj.w * vv.y;
            acc[3].z += pj.w * vv.z; acc[3].w += pj.w * vv.w;
        }
    }

#pragma unroll
    for (int qq = 0; qq < 4; qq++) {
        float inv = 1.f / l[qq];
        int row = q0 + warp * 4 + qq;
        float o0 = acc[qq].x * inv, o1 = acc[qq].y * inv;
        float o2 = acc[qq].z * inv, o3 = acc[qq].w * inv;
        __nv_bfloat16 h0 = __float2bfloat16(o0), h1 = __float2bfloat16(o1);
        __nv_bfloat16 h2 = __float2bfloat16(o2), h3 = __float2bfloat16(o3);
        __nv_bfloat162 H0, H1, L0, L1;
        H0.x = h0; H0.y = h1; H1.x = h2; H1.y = h3;
        L0.x = __float2bfloat16(o0 - __bfloat162float(h0));
        L0.y = __float2bfloat16(o1 - __bfloat162float(h1));
        L1.x = __float2bfloat16(o2 - __bfloat162float(h2));
        L1.y = __float2bfloat16(o3 - __bfloat162float(h3));
        size_t base = (size_t)row * DIM + head * HD + lane * 4;
        *(__nv_bfloat162*)&Oh[base]     = H0;
        *(__nv_bfloat162*)&Oh[base + 2] = H1;
        *(__nv_bfloat162*)&Ol[base]     = L0;
        *(__nv_bfloat162*)&Ol[base + 2] = L1;
    }
}

// ======================= launch =======================
extern "C" void kernel_launch(void* const* d_in, const int* in_sizes, int n_in,
                              void* d_out, int out_size) {
    const float* x     = (const float*)d_in[0];
    const float* freqs = (const float*)d_in[1];
    const float* q_w   = (const float*)d_in[2];
    const float* q_b   = (const float*)d_in[3];
    const float* k_w   = (const float*)d_in[4];
    const float* k_b   = (const float*)d_in[5];
    const float* v_w   = (const float*)d_in[6];
    const float* v_b   = (const float*)d_in[7];
    const float* o_w   = (const float*)d_in[8];
    const float* o_b   = (const float*)d_in[9];
    const float* nqw   = (const float*)d_in[10];
    const float* nkw   = (const float*)d_in[11];

    float *gq, *gk, *gv;
    __nv_bfloat16 *xh, *xl, *oh, *ol, *wh, *wl;
    cudaGetSymbolAddress((void**)&gq, g_q);
    cudaGetSymbolAddress((void**)&gk, g_k);
    cudaGetSymbolAddress((void**)&gv, g_v);
    cudaGetSymbolAddress((void**)&xh, g_xh);
    cudaGetSymbolAddress((void**)&xl, g_xl);
    cudaGetSymbolAddress((void**)&oh, g_oh);
    cudaGetSymbolAddress((void**)&ol, g_ol);
    cudaGetSymbolAddress((void**)&wh, g_wh);
    cudaGetSymbolAddress((void**)&wl, g_wl);

    const size_t WSZ = (size_t)DIM * DIM;
    __nv_bfloat16 *qwh = wh + 0 * WSZ, *kwh = wh + 1 * WSZ, *vwh = wh + 2 * WSZ, *owh = wh + 3 * WSZ;
    __nv_bfloat16 *qwl = wl + 0 * WSZ, *kwl = wl + 1 * WSZ, *vwl = wl + 2 * WSZ, *owl = wl + 3 * WSZ;

    // splits
    int nx4 = TS * DIM / 4, nw4 = DIM * DIM / 4;
    split_kernel<<<(nx4 + 255) / 256, 256>>>(x, xh, xl, nx4);
    split_kernel<<<(nw4 + 255) / 256, 256>>>(q_w, qwh, qwl, nw4);
    split_kernel<<<(nw4 + 255) / 256, 256>>>(k_w, kwh, kwl, nw4);
    split_kernel<<<(nw4 + 255) / 256, 256>>>(v_w, vwh, vwl, nw4);
    split_kernel<<<(nw4 + 255) / 256, 256>>>(o_w, owh, owl, nw4);

    // mma.sync GEMMs
    cudaFuncSetAttribute(gemm_mma, cudaFuncAttributeMaxDynamicSharedMemorySize,
                         GEMM_SMEM_BYTES);
    dim3 ggrid(DIM / 128, TS / 128);
    gemm_mma<<<ggrid, 256, GEMM_SMEM_BYTES>>>(xh, xl, qwh, qwl, q_b, gq, TS, DIM, DIM);
    gemm_mma<<<ggrid, 256, GEMM_SMEM_BYTES>>>(xh, xl, kwh, kwl, k_b, gk, TS, DIM, DIM);
    gemm_mma<<<ggrid, 256, GEMM_SMEM_BYTES>>>(xh, xl, vwh, vwl, v_b, gv, TS, DIM, DIM);

    norm_rope_kernel<<<dim3(TS, 2), 256>>>(gq, gk, freqs, nqw, nkw);

    const int KROW = HD + 4;
    size_t asmem = (size_t)(QB * HD + 2 * KB * KROW + 8 * KB * 4) * sizeof(float);
    cudaFuncSetAttribute(attn_kernel, cudaFuncAttributeMaxDynamicSharedMemorySize, (int)asmem);
    attn_kernel<<<dim3(TS / QB, NH), 256, asmem>>>(gq, gk, gv, oh, ol);

    gemm_mma<<<ggrid, 256, GEMM_SMEM_BYTES>>>(oh, ol, owh, owl, o_b, (float*)d_out, TS, DIM, DIM);
}

// round 4
// speedup vs baseline: 3.5072x; 2.4084x over previous
#include <cuda_runtime.h>
#include <cuda_bf16.h>
#include <cstdint>

#define TS   3584
#define DIM  1536
#define NH   12
#define HD   128
#define VS   1792
#define TPF  448
#define NW   28
#define EPS  1e-6f
#define SCALE 0.08838834764831845f   // 1/sqrt(128)

// -------- scratch (device globals; no allocations allowed) --------
__device__ float g_q[(size_t)TS * DIM];
__device__ float g_k[(size_t)TS * DIM];
__device__ __nv_bfloat16 g_xh[(size_t)TS * DIM];
__device__ __nv_bfloat16 g_xl[(size_t)TS * DIM];
__device__ __nv_bfloat16 g_qh[(size_t)TS * DIM];
__device__ __nv_bfloat16 g_ql[(size_t)TS * DIM];
__device__ __nv_bfloat16 g_kh[(size_t)TS * DIM];
__device__ __nv_bfloat16 g_kl[(size_t)TS * DIM];
__device__ __nv_bfloat16 g_vh[(size_t)TS * DIM];
__device__ __nv_bfloat16 g_vl[(size_t)TS * DIM];
__device__ __nv_bfloat16 g_oh[(size_t)TS * DIM];
__device__ __nv_bfloat16 g_ol[(size_t)TS * DIM];
__device__ __nv_bfloat16 g_wh[4][(size_t)DIM * DIM];
__device__ __nv_bfloat16 g_wl[4][(size_t)DIM * DIM];

// ======================= PTX helpers =======================
__device__ __forceinline__ uint32_t s2u(const void* p) {
    uint32_t a;
    asm("{ .reg .u64 t; cvta.to.shared.u64 t, %1; cvt.u32.u64 %0, t; }"
        : "=r"(a) : "l"(p));
    return a;
}
__device__ __forceinline__ void ldsm_x4(uint32_t* r, uint32_t addr) {
    asm volatile("ldmatrix.sync.aligned.m8n8.x4.shared.b16 {%0,%1,%2,%3}, [%4];"
                 : "=r"(r[0]), "=r"(r[1]), "=r"(r[2]), "=r"(r[3]) : "r"(addr));
}
__device__ __forceinline__ void ldsm_x4_t(uint32_t* r, uint32_t addr) {
    asm volatile("ldmatrix.sync.aligned.m8n8.x4.trans.shared.b16 {%0,%1,%2,%3}, [%4];"
                 : "=r"(r[0]), "=r"(r[1]), "=r"(r[2]), "=r"(r[3]) : "r"(addr));
}
__device__ __forceinline__ void mma16816(float* c, const uint32_t* a, const uint32_t* b) {
    asm volatile(
        "mma.sync.aligned.m16n8k16.row.col.f32.bf16.bf16.f32 "
        "{%0,%1,%2,%3}, {%4,%5,%6,%7}, {%8,%9}, {%0,%1,%2,%3};"
        : "+f"(c[0]), "+f"(c[1]), "+f"(c[2]), "+f"(c[3])
        : "r"(a[0]), "r"(a[1]), "r"(a[2]), "r"(a[3]), "r"(b[0]), "r"(b[1]));
}
__device__ __forceinline__ void cp16(uint32_t dst, const void* src) {
    asm volatile("cp.async.ca.shared.global [%0], [%1], 16;"
                 :: "r"(dst), "l"(src) : "memory");
}
__device__ __forceinline__ void cp_commit() {
    asm volatile("cp.async.commit_group;" ::: "memory");
}
template <int N>
__device__ __forceinline__ void cp_wait() {
    asm volatile("cp.async.wait_group %0;" :: "n"(N) : "memory");
}
__device__ __forceinline__ uint32_t packbf(float a, float b) {
    __nv_bfloat162 h;
    h.x = __float2bfloat16(a);
    h.y = __float2bfloat16(b);
    return *(uint32_t*)&h;
}

// ======================= fp32 -> (hi, lo) bf16 split =======================
__global__ __launch_bounds__(256)
void split_kernel(const float* __restrict__ in,
                  __nv_bfloat16* __restrict__ hi,
                  __nv_bfloat16* __restrict__ lo, int n4) {
    int i = blockIdx.x * 256 + threadIdx.x;
    if (i >= n4) return;
    float4 v = ((const float4*)in)[i];
    __nv_bfloat16 h0 = __float2bfloat16(v.x);
    __nv_bfloat16 h1 = __float2bfloat16(v.y);
    __nv_bfloat16 h2 = __float2bfloat16(v.z);
    __nv_bfloat16 h3 = __float2bfloat16(v.w);
    __nv_bfloat162 H0, H1, L0, L1;
    H0.x = h0; H0.y = h1; H1.x = h2; H1.y = h3;
    L0.x = __float2bfloat16(v.x - __bfloat162float(h0));
    L0.y = __float2bfloat16(v.y - __bfloat162float(h1));
    L1.x = __float2bfloat16(v.z - __bfloat162float(h2));
    L1.y = __float2bfloat16(v.w - __bfloat162float(h3));
    ((__nv_bfloat162*)hi)[2 * i]     = H0;
    ((__nv_bfloat162*)hi)[2 * i + 1] = H1;
    ((__nv_bfloat162*)lo)[2 * i]     = L0;
    ((__nv_bfloat162*)lo)[2 * i + 1] = L1;
}

// ======================= mma.sync split-bf16 GEMM (cp.async pipeline) ======
// C = A @ W^T + bias via Ah*Wh + Al*Wh + Ah*Wl. 128x128 tile, K chunks of 32.
#define SSTR 40                   // smem row stride (elems), 80 B
#define TILE_E (128 * SSTR)       // 5120 elems
#define TILE_B (TILE_E * 2)       // bytes
#define BUF_E  (4 * TILE_E)
#define GEMM_SMEM_BYTES (2 * BUF_E * 2)

__global__ __launch_bounds__(256)
void gemm_mma(const __nv_bfloat16* __restrict__ Ah, const __nv_bfloat16* __restrict__ Al,
              const __nv_bfloat16* __restrict__ Wh, const __nv_bfloat16* __restrict__ Wl,
              const float* __restrict__ bias,
              float* __restrict__ Cf,
              __nv_bfloat16* __restrict__ Ch, __nv_bfloat16* __restrict__ Cl,
              int M, int N, int K) {
    extern __shared__ __nv_bfloat16 sm[];
    const int tid  = threadIdx.x;
    const int warp = tid >> 5, lane = tid & 31;
    const int wm   = warp & 1;
    const int wn   = warp >> 1;
    const int m0   = blockIdx.y * 128, n0 = blockIdx.x * 128;
    const uint32_t sbase = s2u(sm);

    float acc[4][4][4];
#pragma unroll
    for (int i = 0; i < 4; i++)
#pragma unroll
        for (int j = 0; j < 4; j++)
#pragma unroll
            for (int k = 0; k < 4; k++) acc[i][j][k] = 0.f;

    const __nv_bfloat16* srcs[4] = {Ah, Al, Wh, Wl};

    auto issue_chunk = [&](int c, int b) {
#pragma unroll
        for (int j = 0; j < 8; j++) {
            int i = tid + j * 256;            // 0..2047
            int arr = i >> 9;
            int idx = i & 511;
            int row = idx >> 2, seg = idx & 3;
            const __nv_bfloat16* src = srcs[arr] +
                (size_t)((arr < 2 ? m0 : n0) + row) * K + c * 32 + seg * 8;
            uint32_t dst = sbase + (uint32_t)(b * BUF_E + arr * TILE_E + row * SSTR + seg * 8) * 2;
            cp16(dst, src);
        }
        cp_commit();
    };

    const int NC = K / 32;
    issue_chunk(0, 0);

    const uint32_t arow = (uint32_t)(wm * 64 + (lane & 15));
    const uint32_t acol = (uint32_t)((lane >> 4) * 16);
    const uint32_t bro  = (uint32_t)((lane & 7) + 8 * ((lane >> 4) & 1));
    const uint32_t bco  = (uint32_t)(((lane >> 3) & 1) * 16);

    for (int c = 0; c < NC; c++) {
        if (c + 1 < NC) { issue_chunk(c + 1, (c + 1) & 1); cp_wait<1>(); }
        else            { cp_wait<0>(); }
        __syncthreads();
        const uint32_t bb = sbase + (uint32_t)((c & 1) * BUF_E) * 2;
#pragma unroll
        for (int ks = 0; ks < 2; ks++) {
            uint32_t aH[4][4], aL[4][4], bH[8], bL[8];
            const uint32_t aoff = arow * (SSTR * 2) + ks * 32 + acol;
#pragma unroll
            for (int mt = 0; mt < 4; mt++)
                ldsm_x4(aH[mt], bb + 0 * TILE_B + aoff + mt * 16 * (SSTR * 2));
#pragma unroll
            for (int p = 0; p < 2; p++) {
                uint32_t boff = (uint32_t)(wn * 32 + p * 16 + bro) * (SSTR * 2) + ks * 32 + bco;
                ldsm_x4(&bH[4 * p], bb + 2 * TILE_B + boff);
            }
#pragma unroll
            for (int mt = 0; mt < 4; mt++)
#pragma unroll
                for (int nt = 0; nt < 4; nt++)
                    mma16816(acc[mt][nt], aH[mt], &bH[2 * nt]);
#pragma unroll
            for (int mt = 0; mt < 4; mt++)
                ldsm_x4(aL[mt], bb + 1 * TILE_B + aoff + mt * 16 * (SSTR * 2));
#pragma unroll
            for (int mt = 0; mt < 4; mt++)
#pragma unroll
                for (int nt = 0; nt < 4; nt++)
                    mma16816(acc[mt][nt], aL[mt], &bH[2 * nt]);
#pragma unroll
            for (int p = 0; p < 2; p++) {
                uint32_t boff = (uint32_t)(wn * 32 + p * 16 + bro) * (SSTR * 2) + ks * 32 + bco;
                ldsm_x4(&bL[4 * p], bb + 3 * TILE_B + boff);
            }
#pragma unroll
            for (int mt = 0; mt < 4; mt++)
#pragma unroll
                for (int nt = 0; nt < 4; nt++)
                    mma16816(acc[mt][nt], aH[mt], &bL[2 * nt]);
        }
        __syncthreads();
    }

    // ---- epilogue ----
    const int row_base = m0 + wm * 64 + (lane >> 2);
    const int col_base = n0 + wn * 32 + (lane & 3) * 2;
#pragma unroll
    for (int mt = 0; mt < 4; mt++) {
#pragma unroll
        for (int nt = 0; nt < 4; nt++) {
            int r = row_base + mt * 16;
            int cc = col_base + nt * 8;
            float bx = bias[cc], by = bias[cc + 1];
            float v00 = acc[mt][nt][0] + bx, v01 = acc[mt][nt][1] + by;
            float v10 = acc[mt][nt][2] + bx, v11 = acc[mt][nt][3] + by;
            if (Cf) {
                *(float2*)(Cf + (size_t)r * N + cc)       = make_float2(v00, v01);
                *(float2*)(Cf + (size_t)(r + 8) * N + cc) = make_float2(v10, v11);
            } else {
                uint32_t h0 = packbf(v00, v01);
                uint32_t h1 = packbf(v10, v11);
                __nv_bfloat162 H0 = *(__nv_bfloat162*)&h0;
                __nv_bfloat162 H1 = *(__nv_bfloat162*)&h1;
                uint32_t l0 = packbf(v00 - __bfloat162float(H0.x), v01 - __bfloat162float(H0.y));
                uint32_t l1 = packbf(v10 - __bfloat162float(H1.x), v11 - __bfloat162float(H1.y));
                *(uint32_t*)(Ch + (size_t)r * N + cc)       = h0;
                *(uint32_t*)(Ch + (size_t)(r + 8) * N + cc) = h1;
                *(uint32_t*)(Cl + (size_t)r * N + cc)       = l0;
                *(uint32_t*)(Cl + (size_t)(r + 8) * N + cc) = l1;
            }
        }
    }
}

// ======================= RMSNorm + RoPE -> bf16 hi/lo =======================
__global__ __launch_bounds__(256)
void norm_rope_kernel(const float* __restrict__ q, const float* __restrict__ k,
                      const float* __restrict__ freqs,
                      const float* __restrict__ nqw, const float* __restrict__ nkw,
                      __nv_bfloat16* __restrict__ QH, __nv_bfloat16* __restrict__ QL,
                      __nv_bfloat16* __restrict__ KH, __nv_bfloat16* __restrict__ KL) {
    const int row = blockIdx.x;
    const float* x = (blockIdx.y == 0 ? q : k) + (size_t)row * DIM;
    const float* w = (blockIdx.y == 0) ? nqw : nkw;
    __nv_bfloat16* OH = (blockIdx.y == 0) ? QH : KH;
    __nv_bfloat16* OL = (blockIdx.y == 0) ? QL : KL;
    const int tid = threadIdx.x;

    float ss = 0.f;
    for (int i = tid; i < DIM; i += 256) { float v = x[i]; ss += v * v; }
#pragma unroll
    for (int o = 16; o > 0; o >>= 1) ss += __shfl_xor_sync(~0u, ss, o);
    __shared__ float warpsum[8];
    if ((tid & 31) == 0) warpsum[tid >> 5] = ss;
    __syncthreads();
    float tot = 0.f;
#pragma unroll
    for (int i = 0; i < 8; i++) tot += warpsum[i];
    const float rs = rsqrtf(tot / (float)DIM + EPS);

    const int tv = row % VS;
    const int f  = tv / TPF;
    const int r  = tv % TPF;
    const int hh = r / NW;
    const int ww = r % NW;

    for (int p = tid; p < DIM / 2; p += 256) {
        int c = p & 63;
        int idx = (c < 22) ? f : ((c < 43) ? hh : ww);
        float ang = freqs[idx * 64 + c];
        float sn, cs;
        sincosf(ang, &sn, &cs);
        float x0 = x[2 * p]     * rs * w[2 * p];
        float x1 = x[2 * p + 1] * rs * w[2 * p + 1];
        float r0 = x0 * cs - x1 * sn;
        float r1 = x0 * sn + x1 * cs;
        uint32_t h = packbf(r0, r1);
        __nv_bfloat162 H = *(__nv_bfloat162*)&h;
        uint32_t l = packbf(r0 - __bfloat162float(H.x), r1 - __bfloat162float(H.y));
        *(uint32_t*)(OH + (size_t)row * DIM + 2 * p) = h;
        *(uint32_t*)(OL + (size_t)row * DIM + 2 * p) = l;
    }
}

// ======================= mma.sync flash attention =======================
// 64 queries x 1 head per block, 4 warps (m16 each), 32-key tiles,
// single softmax over union keyset (1792 same-view + 448 cross-view-same-frame).
#define ASTR 136
#define AQR  (64 * ASTR)           // one Q array (elems)
#define ATL  (32 * ASTR)           // one K/V tile (elems)
#define ASTAGE (4 * ATL)           // Kh,Kl,Vh,Vl
#define ATT_SMEM_BYTES ((2 * AQR + 2 * ASTAGE) * 2)

__global__ __launch_bounds__(128)
void attn_mma(const __nv_bfloat16* __restrict__ Qh, const __nv_bfloat16* __restrict__ Ql,
              const __nv_bfloat16* __restrict__ Kh, const __nv_bfloat16* __restrict__ Kl,
              const __nv_bfloat16* __restrict__ Vh, const __nv_bfloat16* __restrict__ Vl,
              __nv_bfloat16* __restrict__ Oh, __nv_bfloat16* __restrict__ Ol) {
    extern __shared__ __nv_bfloat16 smb[];
    const uint32_t sbase = s2u(smb);
    const int head = blockIdx.y;
    const int q0   = blockIdx.x * 64;
    const int v    = q0 / VS;
    const int f    = (q0 % VS) / TPF;
    const int col0 = head * HD;
    const int tid  = threadIdx.x;
    const int warp = tid >> 5, lane = tid & 31;

    // ---- load Q tiles (hi/lo) into smem ----
    for (int i = tid; i < 1024; i += 128) {
        int r = i >> 4, seg = i & 15;
        *(uint4*)&smb[r * ASTR + seg * 8] =
            *(const uint4*)&Qh[(size_t)(q0 + r) * DIM + col0 + seg * 8];
        *(uint4*)&smb[AQR + r * ASTR + seg * 8] =
            *(const uint4*)&Ql[(size_t)(q0 + r) * DIM + col0 + seg * 8];
    }

    const int baseA = v * VS;
    const int baseB = (1 - v) * VS + f * TPF;
    const int NT_A  = VS / 32;          // 56
    const int NT    = (VS + TPF) / 32;  // 70

    const __nv_bfloat16* ptrs[4] = {Kh, Kl, Vh, Vl};

    auto issue_tile = [&](int t, int s) {
        int kb = (t < NT_A) ? (baseA + t * 32) : (baseB + (t - NT_A) * 32);
#pragma unroll
        for (int j = 0; j < 16; j++) {
            int i = tid + j * 128;        // 0..2047
            int arr = i >> 9;
            int idx = i & 511;
            int r = idx >> 4, seg = idx & 15;
            const __nv_bfloat16* src = ptrs[arr] + (size_t)(kb + r) * DIM + col0 + seg * 8;
            uint32_t dst = sbase + (uint32_t)(2 * AQR + s * ASTAGE + arr * ATL + r * ASTR + seg * 8) * 2;
            cp16(dst, src);
        }
        cp_commit();
    };

    issue_tile(0, 0);

    float m[2] = {-1e30f, -1e30f};
    float l[2] = {0.f, 0.f};
    float acc[16][4];
#pragma unroll
    for (int nt = 0; nt < 16; nt++)
#pragma unroll
        for (int j = 0; j < 4; j++) acc[nt][j] = 0.f;

    const uint32_t q_aoff = (uint32_t)(warp * 16 + (lane & 15)) * (ASTR * 2)
                          + (uint32_t)((lane >> 4) * 16);
    const uint32_t k_bro  = (uint32_t)((lane & 7) + 8 * ((lane >> 4) & 1));
    const uint32_t k_bco  = (uint32_t)(((lane >> 3) & 1) * 16);
    const uint32_t v_row  = (uint32_t)(lane & 15);
    const uint32_t v_cofs = (uint32_t)(8 * ((lane >> 4) & 1));
    __syncthreads();   // Q ready (plain stores) before first tile compute

    for (int t = 0; t < NT; t++) {
        if (t + 1 < NT) { issue_tile(t + 1, (t + 1) & 1); cp_wait<1>(); }
        else            { cp_wait<0>(); }
        __syncthreads();
        const uint32_t st = sbase + (uint32_t)(2 * AQR + (t & 1) * ASTAGE) * 2;
        const uint32_t khb = st, klb = st + ATL * 2, vhb = st + 2 * ATL * 2, vlb = st + 3 * ATL * 2;

        // ---- S = Q K^T (3 split terms) ----
        float S[4][4];
#pragma unroll
        for (int nt = 0; nt < 4; nt++)
#pragma unroll
            for (int j = 0; j < 4; j++) S[nt][j] = 0.f;

#pragma unroll
        for (int ks = 0; ks < 8; ks++) {
            uint32_t aQh[4], aQl[4], bKh[8], bKl[8];
            ldsm_x4(aQh, sbase + q_aoff + ks * 32);
            ldsm_x4(aQl, sbase + AQR * 2 + q_aoff + ks * 32);
#pragma unroll
            for (int p = 0; p < 2; p++) {
                uint32_t boff = (uint32_t)(p * 16 + k_bro) * (ASTR * 2) + ks * 32 + k_bco;
                ldsm_x4(&bKh[4 * p], khb + boff);
                ldsm_x4(&bKl[4 * p], klb + boff);
            }
#pragma unroll
            for (int nt = 0; nt < 4; nt++) {
                mma16816(S[nt], aQh, &bKh[2 * nt]);
                mma16816(S[nt], aQh, &bKl[2 * nt]);
                mma16816(S[nt], aQl, &bKh[2 * nt]);
            }
        }

        // ---- online softmax (rows: lane>>2 and +8) ----
#pragma unroll
        for (int nt = 0; nt < 4; nt++)
#pragma unroll
            for (int j = 0; j < 4; j++) S[nt][j] *= SCALE;

        uint32_t ph[4][2], pl[4][2];
#pragma unroll
        for (int j = 0; j < 2; j++) {
            float mx = -1e30f;
#pragma unroll
            for (int nt = 0; nt < 4; nt++)
                mx = fmaxf(mx, fmaxf(S[nt][2 * j], S[nt][2 * j + 1]));
            mx = fmaxf(mx, __shfl_xor_sync(~0u, mx, 1));
            mx = fmaxf(mx, __shfl_xor_sync(~0u, mx, 2));
            float mn = fmaxf(m[j], mx);
            float corr = __expf(m[j] - mn);
            m[j] = mn;
            float rs = 0.f;
#pragma unroll
            for (int nt = 0; nt < 4; nt++) {
                float e0 = __expf(S[nt][2 * j]     - mn);
                float e1 = __expf(S[nt][2 * j + 1] - mn);
                S[nt][2 * j] = e0; S[nt][2 * j + 1] = e1;
                rs += e0 + e1;
            }
            rs += __shfl_xor_sync(~0u, rs, 1);
            rs += __shfl_xor_sync(~0u, rs, 2);
            l[j] = l[j] * corr + rs;
#pragma unroll
            for (int nt = 0; nt < 16; nt++) {
                acc[nt][2 * j]     *= corr;
                acc[nt][2 * j + 1] *= corr;
            }
        }
#pragma unroll
        for (int nt = 0; nt < 4; nt++) {
#pragma unroll
            for (int j = 0; j < 2; j++) {
                float e0 = S[nt][2 * j], e1 = S[nt][2 * j + 1];
                uint32_t h = packbf(e0, e1);
                __nv_bfloat162 H = *(__nv_bfloat162*)&h;
                ph[nt][j] = h;
                pl[nt][j] = packbf(e0 - __bfloat162float(H.x), e1 - __bfloat162float(H.y));
            }
        }

        // ---- out += P V (3 split terms) ----
#pragma unroll
        for (int ks2 = 0; ks2 < 2; ks2++) {
            uint32_t aPh[4] = {ph[2 * ks2][0], ph[2 * ks2][1], ph[2 * ks2 + 1][0], ph[2 * ks2 + 1][1]};
            uint32_t aPl[4] = {pl[2 * ks2][0], pl[2 * ks2][1], pl[2 * ks2 + 1][0], pl[2 * ks2 + 1][1]};
#pragma unroll
            for (int dp = 0; dp < 8; dp++) {
                uint32_t bVh[4], bVl[4];
                uint32_t voff = (uint32_t)(ks2 * 16 + v_row) * (ASTR * 2)
                              + (uint32_t)(dp * 16 + v_cofs) * 2;
                ldsm_x4_t(bVh, vhb + voff);
                mma16816(acc[2 * dp],     aPh, &bVh[0]);
                mma16816(acc[2 * dp + 1], aPh, &bVh[2]);
                mma16816(acc[2 * dp],     aPl, &bVh[0]);
                mma16816(acc[2 * dp + 1], aPl, &bVh[2]);
                ldsm_x4_t(bVl, vlb + voff);
                mma16816(acc[2 * dp],     aPh, &bVl[0]);
                mma16816(acc[2 * dp + 1], aPh, &bVl[2]);
            }
        }
        __syncthreads();
    }

    // ---- epilogue ----
#pragma unroll
    for (int j = 0; j < 2; j++) {
        float inv = 1.f / l[j];
        int row = q0 + warp * 16 + (lane >> 2) + 8 * j;
#pragma unroll
        for (int nt = 0; nt < 16; nt++) {
            float o0 = acc[nt][2 * j] * inv;
            float o1 = acc[nt][2 * j + 1] * inv;
            uint32_t h = packbf(o0, o1);
            __nv_bfloat162 H = *(__nv_bfloat162*)&h;
            uint32_t lo = packbf(o0 - __bfloat162float(H.x), o1 - __bfloat162float(H.y));
            size_t off = (size_t)row * DIM + col0 + nt * 8 + 2 * (lane & 3);
            *(uint32_t*)(Oh + off) = h;
            *(uint32_t*)(Ol + off) = lo;
        }
    }
}

// ======================= launch =======================
extern "C" void kernel_launch(void* const* d_in, const int* in_sizes, int n_in,
                              void* d_out, int out_size) {
    const float* x     = (const float*)d_in[0];
    const float* freqs = (const float*)d_in[1];
    const float* q_w   = (const float*)d_in[2];
    const float* q_b   = (const float*)d_in[3];
    const float* k_w   = (const float*)d_in[4];
    const float* k_b   = (const float*)d_in[5];
    const float* v_w   = (const float*)d_in[6];
    const float* v_b   = (const float*)d_in[7];
    const float* o_w   = (const float*)d_in[8];
    const float* o_b   = (const float*)d_in[9];
    const float* nqw   = (const float*)d_in[10];
    const float* nkw   = (const float*)d_in[11];

    float *gq, *gk;
    __nv_bfloat16 *xh, *xl, *qh, *ql, *kh, *kl, *vh, *vl, *oh, *ol, *wh, *wl;
    cudaGetSymbolAddress((void**)&gq, g_q);
    cudaGetSymbolAddress((void**)&gk, g_k);
    cudaGetSymbolAddress((void**)&xh, g_xh);
    cudaGetSymbolAddress((void**)&xl, g_xl);
    cudaGetSymbolAddress((void**)&qh, g_qh);
    cudaGetSymbolAddress((void**)&ql, g_ql);
    cudaGetSymbolAddress((void**)&kh, g_kh);
    cudaGetSymbolAddress((void**)&kl, g_kl);
    cudaGetSymbolAddress((void**)&vh, g_vh);
    cudaGetSymbolAddress((void**)&vl, g_vl);
    cudaGetSymbolAddress((void**)&oh, g_oh);
    cudaGetSymbolAddress((void**)&ol, g_ol);
    cudaGetSymbolAddress((void**)&wh, g_wh);
    cudaGetSymbolAddress((void**)&wl, g_wl);

    const size_t WSZ = (size_t)DIM * DIM;
    __nv_bfloat16 *qwh = wh + 0 * WSZ, *kwh = wh + 1 * WSZ, *vwh = wh + 2 * WSZ, *owh = wh + 3 * WSZ;
    __nv_bfloat16 *qwl = wl + 0 * WSZ, *kwl = wl + 1 * WSZ, *vwl = wl + 2 * WSZ, *owl = wl + 3 * WSZ;

    int nx4 = TS * DIM / 4, nw4 = DIM * DIM / 4;
    split_kernel<<<(nx4 + 255) / 256, 256>>>(x, xh, xl, nx4);
    split_kernel<<<(nw4 + 255) / 256, 256>>>(q_w, qwh, qwl, nw4);
    split_kernel<<<(nw4 + 255) / 256, 256>>>(k_w, kwh, kwl, nw4);
    split_kernel<<<(nw4 + 255) / 256, 256>>>(v_w, vwh, vwl, nw4);
    split_kernel<<<(nw4 + 255) / 256, 256>>>(o_w, owh, owl, nw4);

    cudaFuncSetAttribute(gemm_mma, cudaFuncAttributeMaxDynamicSharedMemorySize,
                         GEMM_SMEM_BYTES);
    dim3 ggrid(DIM / 128, TS / 128);
    gemm_mma<<<ggrid, 256, GEMM_SMEM_BYTES>>>(xh, xl, qwh, qwl, q_b, gq, nullptr, nullptr, TS, DIM, DIM);
    gemm_mma<<<ggrid, 256, GEMM_SMEM_BYTES>>>(xh, xl, kwh, kwl, k_b, gk, nullptr, nullptr, TS, DIM, DIM);
    gemm_mma<<<ggrid, 256, GEMM_SMEM_BYTES>>>(xh, xl, vwh, vwl, v_b, nullptr, vh, vl, TS, DIM, DIM);

    norm_rope_kernel<<<dim3(TS, 2), 256>>>(gq, gk, freqs, nqw, nkw, qh, ql, kh, kl);

    cudaFuncSetAttribute(attn_mma, cudaFuncAttributeMaxDynamicSharedMemorySize,
                         ATT_SMEM_BYTES);
    attn_mma<<<dim3(TS / 64, NH), 128, ATT_SMEM_BYTES>>>(qh, ql, kh, kl, vh, vl, oh, ol);

    gemm_mma<<<ggrid, 256, GEMM_SMEM_BYTES>>>(oh, ol, owh, owl, o_b, (float*)d_out, nullptr, nullptr, TS, DIM, DIM);
}

// round 5
// speedup vs baseline: 3.5323x; 1.0072x over previous
#include <cuda_runtime.h>
#include <cuda_bf16.h>
#include <cstdint>

#define TS   3584
#define DIM  1536
#define NH   12
#define HD   128
#define VS   1792
#define TPF  448
#define NW   28
#define EPS  1e-6f
#define SCALE 0.08838834764831845f   // 1/sqrt(128)

// -------- scratch (device globals; no allocations allowed) --------
__device__ float g_q[(size_t)TS * DIM];
__device__ float g_k[(size_t)TS * DIM];
__device__ __nv_bfloat16 g_xh[(size_t)TS * DIM];
__device__ __nv_bfloat16 g_xl[(size_t)TS * DIM];
__device__ __nv_bfloat16 g_qh[(size_t)TS * DIM];
__device__ __nv_bfloat16 g_ql[(size_t)TS * DIM];
__device__ __nv_bfloat16 g_kh[(size_t)TS * DIM];
__device__ __nv_bfloat16 g_kl[(size_t)TS * DIM];
__device__ __nv_bfloat16 g_vh[(size_t)TS * DIM];
__device__ __nv_bfloat16 g_vl[(size_t)TS * DIM];
__device__ __nv_bfloat16 g_oh[(size_t)TS * DIM];
__device__ __nv_bfloat16 g_ol[(size_t)TS * DIM];
__device__ __nv_bfloat16 g_wh[4][(size_t)DIM * DIM];
__device__ __nv_bfloat16 g_wl[4][(size_t)DIM * DIM];

// ======================= PTX helpers =======================
__device__ __forceinline__ uint32_t s2u(const void* p) {
    uint32_t a;
    asm("{ .reg .u64 t; cvta.to.shared.u64 t, %1; cvt.u32.u64 %0, t; }"
        : "=r"(a) : "l"(p));
    return a;
}
__device__ __forceinline__ void ldsm_x4(uint32_t* r, uint32_t addr) {
    asm volatile("ldmatrix.sync.aligned.m8n8.x4.shared.b16 {%0,%1,%2,%3}, [%4];"
                 : "=r"(r[0]), "=r"(r[1]), "=r"(r[2]), "=r"(r[3]) : "r"(addr));
}
__device__ __forceinline__ void ldsm_x4_t(uint32_t* r, uint32_t addr) {
    asm volatile("ldmatrix.sync.aligned.m8n8.x4.trans.shared.b16 {%0,%1,%2,%3}, [%4];"
                 : "=r"(r[0]), "=r"(r[1]), "=r"(r[2]), "=r"(r[3]) : "r"(addr));
}
__device__ __forceinline__ void mma16816(float* c, const uint32_t* a, const uint32_t* b) {
    asm volatile(
        "mma.sync.aligned.m16n8k16.row.col.f32.bf16.bf16.f32 "
        "{%0,%1,%2,%3}, {%4,%5,%6,%7}, {%8,%9}, {%0,%1,%2,%3};"
        : "+f"(c[0]), "+f"(c[1]), "+f"(c[2]), "+f"(c[3])
        : "r"(a[0]), "r"(a[1]), "r"(a[2]), "r"(a[3]), "r"(b[0]), "r"(b[1]));
}
__device__ __forceinline__ void cp16(uint32_t dst, const void* src) {
    asm volatile("cp.async.ca.shared.global [%0], [%1], 16;"
                 :: "r"(dst), "l"(src) : "memory");
}
__device__ __forceinline__ void cp_commit() {
    asm volatile("cp.async.commit_group;" ::: "memory");
}
template <int N>
__device__ __forceinline__ void cp_wait() {
    asm volatile("cp.async.wait_group %0;" :: "n"(N) : "memory");
}
__device__ __forceinline__ uint32_t packbf(float a, float b) {
    __nv_bfloat162 h;
    h.x = __float2bfloat16(a);
    h.y = __float2bfloat16(b);
    return *(uint32_t*)&h;
}

// ======================= fp32 -> (hi, lo) bf16 splits =======================
__device__ __forceinline__ void split_one(const float* __restrict__ in,
                                          __nv_bfloat16* __restrict__ hi,
                                          __nv_bfloat16* __restrict__ lo, int i) {
    float4 v = ((const float4*)in)[i];
    __nv_bfloat16 h0 = __float2bfloat16(v.x);
    __nv_bfloat16 h1 = __float2bfloat16(v.y);
    __nv_bfloat16 h2 = __float2bfloat16(v.z);
    __nv_bfloat16 h3 = __float2bfloat16(v.w);
    __nv_bfloat162 H0, H1, L0, L1;
    H0.x = h0; H0.y = h1; H1.x = h2; H1.y = h3;
    L0.x = __float2bfloat16(v.x - __bfloat162float(h0));
    L0.y = __float2bfloat16(v.y - __bfloat162float(h1));
    L1.x = __float2bfloat16(v.z - __bfloat162float(h2));
    L1.y = __float2bfloat16(v.w - __bfloat162float(h3));
    ((__nv_bfloat162*)hi)[2 * i]     = H0;
    ((__nv_bfloat162*)hi)[2 * i + 1] = H1;
    ((__nv_bfloat162*)lo)[2 * i]     = L0;
    ((__nv_bfloat162*)lo)[2 * i + 1] = L1;
}

__global__ __launch_bounds__(256)
void split_kernel(const float* __restrict__ in,
                  __nv_bfloat16* __restrict__ hi,
                  __nv_bfloat16* __restrict__ lo, int n4) {
    int i = blockIdx.x * 256 + threadIdx.x;
    if (i >= n4) return;
    split_one(in, hi, lo, i);
}

__global__ __launch_bounds__(256)
void split4_kernel(const float* __restrict__ s0, const float* __restrict__ s1,
                   const float* __restrict__ s2, const float* __restrict__ s3,
                   __nv_bfloat16* __restrict__ hi, __nv_bfloat16* __restrict__ lo,
                   int n4) {
    int i = blockIdx.x * 256 + threadIdx.x;
    if (i >= n4) return;
    int z = blockIdx.y;
    const float* in = (z == 0) ? s0 : (z == 1) ? s1 : (z == 2) ? s2 : s3;
    split_one(in, hi + (size_t)z * DIM * DIM, lo + (size_t)z * DIM * DIM, i);
}

// ======================= mma.sync split-bf16 GEMM core ======================
#define SSTR 40
#define TILE_E (128 * SSTR)
#define TILE_B (TILE_E * 2)
#define BUF_E  (4 * TILE_E)
#define GEMM_SMEM_BYTES (2 * BUF_E * 2)

struct GemmOut {
    float acc[4][4][4];
};

// core mainloop shared by the two gemm kernels (inlined)
__device__ __forceinline__ void gemm_core(
    const __nv_bfloat16* __restrict__ Ah, const __nv_bfloat16* __restrict__ Al,
    const __nv_bfloat16* __restrict__ Wh, const __nv_bfloat16* __restrict__ Wl,
    int m0, int n0, int K, __nv_bfloat16* sm, GemmOut& out) {
    const int tid  = threadIdx.x;
    const int warp = tid >> 5, lane = tid & 31;
    const int wm   = warp & 1;
    const int wn   = warp >> 1;
    const uint32_t sbase = s2u(sm);

#pragma unroll
    for (int i = 0; i < 4; i++)
#pragma unroll
        for (int j = 0; j < 4; j++)
#pragma unroll
            for (int k = 0; k < 4; k++) out.acc[i][j][k] = 0.f;

    const __nv_bfloat16* srcs[4] = {Ah, Al, Wh, Wl};

    auto issue_chunk = [&](int c, int b) {
#pragma unroll
        for (int j = 0; j < 8; j++) {
            int i = tid + j * 256;
            int arr = i >> 9;
            int idx = i & 511;
            int row = idx >> 2, seg = idx & 3;
            const __nv_bfloat16* src = srcs[arr] +
                (size_t)((arr < 2 ? m0 : n0) + row) * K + c * 32 + seg * 8;
            uint32_t dst = sbase + (uint32_t)(b * BUF_E + arr * TILE_E + row * SSTR + seg * 8) * 2;
            cp16(dst, src);
        }
        cp_commit();
    };

    const int NC = K / 32;
    issue_chunk(0, 0);

    const uint32_t arow = (uint32_t)(wm * 64 + (lane & 15));
    const uint32_t acol = (uint32_t)((lane >> 4) * 16);
    const uint32_t bro  = (uint32_t)((lane & 7) + 8 * ((lane >> 4) & 1));
    const uint32_t bco  = (uint32_t)(((lane >> 3) & 1) * 16);

    for (int c = 0; c < NC; c++) {
        if (c + 1 < NC) { issue_chunk(c + 1, (c + 1) & 1); cp_wait<1>(); }
        else            { cp_wait<0>(); }
        __syncthreads();
        const uint32_t bb = sbase + (uint32_t)((c & 1) * BUF_E) * 2;
#pragma unroll
        for (int ks = 0; ks < 2; ks++) {
            uint32_t aH[4][4], aL[4][4], bH[8], bL[8];
            const uint32_t aoff = arow * (SSTR * 2) + ks * 32 + acol;
#pragma unroll
            for (int mt = 0; mt < 4; mt++)
                ldsm_x4(aH[mt], bb + 0 * TILE_B + aoff + mt * 16 * (SSTR * 2));
#pragma unroll
            for (int p = 0; p < 2; p++) {
                uint32_t boff = (uint32_t)(wn * 32 + p * 16 + bro) * (SSTR * 2) + ks * 32 + bco;
                ldsm_x4(&bH[4 * p], bb + 2 * TILE_B + boff);
            }
#pragma unroll
            for (int mt = 0; mt < 4; mt++)
#pragma unroll
                for (int nt = 0; nt < 4; nt++)
                    mma16816(out.acc[mt][nt], aH[mt], &bH[2 * nt]);
#pragma unroll
            for (int mt = 0; mt < 4; mt++)
                ldsm_x4(aL[mt], bb + 1 * TILE_B + aoff + mt * 16 * (SSTR * 2));
#pragma unroll
            for (int mt = 0; mt < 4; mt++)
#pragma unroll
                for (int nt = 0; nt < 4; nt++)
                    mma16816(out.acc[mt][nt], aL[mt], &bH[2 * nt]);
#pragma unroll
            for (int p = 0; p < 2; p++) {
                uint32_t boff = (uint32_t)(wn * 32 + p * 16 + bro) * (SSTR * 2) + ks * 32 + bco;
                ldsm_x4(&bL[4 * p], bb + 3 * TILE_B + boff);
            }
#pragma unroll
            for (int mt = 0; mt < 4; mt++)
#pragma unroll
                for (int nt = 0; nt < 4; nt++)
                    mma16816(out.acc[mt][nt], aH[mt], &bL[2 * nt]);
        }
        __syncthreads();
    }
}

// ---- fused QKV projection: z = 0 (Q, f32) / 1 (K, f32) / 2 (V, bf16 hi/lo) ----
__global__ __launch_bounds__(256)
void gemm_qkv(const __nv_bfloat16* __restrict__ xh, const __nv_bfloat16* __restrict__ xl,
              const __nv_bfloat16* __restrict__ whb, const __nv_bfloat16* __restrict__ wlb,
              const float* __restrict__ qb, const float* __restrict__ kb,
              const float* __restrict__ vb,
              float* __restrict__ gq, float* __restrict__ gk,
              __nv_bfloat16* __restrict__ vh, __nv_bfloat16* __restrict__ vl) {
    extern __shared__ __nv_bfloat16 sm[];
    const int z  = blockIdx.z;
    const int m0 = blockIdx.y * 128, n0 = blockIdx.x * 128;
    const size_t WSZ = (size_t)DIM * DIM;
    const __nv_bfloat16* Wh = whb + (size_t)z * WSZ;
    const __nv_bfloat16* Wl = wlb + (size_t)z * WSZ;
    const float* bias = (z == 0) ? qb : (z == 1) ? kb : vb;

    GemmOut out;
    gemm_core(xh, xl, Wh, Wl, m0, n0, DIM, sm, out);

    const int warp = threadIdx.x >> 5, lane = threadIdx.x & 31;
    const int row_base = m0 + (warp & 1) * 64 + (lane >> 2);
    const int col_base = n0 + (warp >> 1) * 32 + (lane & 3) * 2;
    float* Cf = (z == 0) ? gq : gk;
#pragma unroll
    for (int mt = 0; mt < 4; mt++) {
#pragma unroll
        for (int nt = 0; nt < 4; nt++) {
            int r = row_base + mt * 16;
            int cc = col_base + nt * 8;
            float bx = bias[cc], by = bias[cc + 1];
            float v00 = out.acc[mt][nt][0] + bx, v01 = out.acc[mt][nt][1] + by;
            float v10 = out.acc[mt][nt][2] + bx, v11 = out.acc[mt][nt][3] + by;
            if (z < 2) {
                *(float2*)(Cf + (size_t)r * DIM + cc)       = make_float2(v00, v01);
                *(float2*)(Cf + (size_t)(r + 8) * DIM + cc) = make_float2(v10, v11);
            } else {
                uint32_t h0 = packbf(v00, v01);
                uint32_t h1 = packbf(v10, v11);
                __nv_bfloat162 H0 = *(__nv_bfloat162*)&h0;
                __nv_bfloat162 H1 = *(__nv_bfloat162*)&h1;
                uint32_t l0 = packbf(v00 - __bfloat162float(H0.x), v01 - __bfloat162float(H0.y));
                uint32_t l1 = packbf(v10 - __bfloat162float(H1.x), v11 - __bfloat162float(H1.y));
                *(uint32_t*)(vh + (size_t)r * DIM + cc)       = h0;
                *(uint32_t*)(vh + (size_t)(r + 8) * DIM + cc) = h1;
                *(uint32_t*)(vl + (size_t)r * DIM + cc)       = l0;
                *(uint32_t*)(vl + (size_t)(r + 8) * DIM + cc) = l1;
            }
        }
    }
}

// ---- O projection (f32 out) ----
__global__ __launch_bounds__(256)
void gemm_o(const __nv_bfloat16* __restrict__ Ah, const __nv_bfloat16* __restrict__ Al,
            const __nv_bfloat16* __restrict__ Wh, const __nv_bfloat16* __restrict__ Wl,
            const float* __restrict__ bias, float* __restrict__ Cf) {
    extern __shared__ __nv_bfloat16 sm[];
    const int m0 = blockIdx.y * 128, n0 = blockIdx.x * 128;
    GemmOut out;
    gemm_core(Ah, Al, Wh, Wl, m0, n0, DIM, sm, out);

    const int warp = threadIdx.x >> 5, lane = threadIdx.x & 31;
    const int row_base = m0 + (warp & 1) * 64 + (lane >> 2);
    const int col_base = n0 + (warp >> 1) * 32 + (lane & 3) * 2;
#pragma unroll
    for (int mt = 0; mt < 4; mt++) {
#pragma unroll
        for (int nt = 0; nt < 4; nt++) {
            int r = row_base + mt * 16;
            int cc = col_base + nt * 8;
            float bx = bias[cc], by = bias[cc + 1];
            *(float2*)(Cf + (size_t)r * DIM + cc) =
                make_float2(out.acc[mt][nt][0] + bx, out.acc[mt][nt][1] + by);
            *(float2*)(Cf + (size_t)(r + 8) * DIM + cc) =
                make_float2(out.acc[mt][nt][2] + bx, out.acc[mt][nt][3] + by);
        }
    }
}

// ======================= RMSNorm + RoPE -> bf16 hi/lo =======================
__global__ __launch_bounds__(256)
void norm_rope_kernel(const float* __restrict__ q, const float* __restrict__ k,
                      const float* __restrict__ freqs,
                      const float* __restrict__ nqw, const float* __restrict__ nkw,
                      __nv_bfloat16* __restrict__ QH, __nv_bfloat16* __restrict__ QL,
                      __nv_bfloat16* __restrict__ KH, __nv_bfloat16* __restrict__ KL) {
    const int row = blockIdx.x;
    const float* x = (blockIdx.y == 0 ? q : k) + (size_t)row * DIM;
    const float* w = (blockIdx.y == 0) ? nqw : nkw;
    __nv_bfloat16* OH = (blockIdx.y == 0) ? QH : KH;
    __nv_bfloat16* OL = (blockIdx.y == 0) ? QL : KL;
    const int tid = threadIdx.x;

    float ss = 0.f;
    for (int i = tid; i < DIM; i += 256) { float v = x[i]; ss += v * v; }
#pragma unroll
    for (int o = 16; o > 0; o >>= 1) ss += __shfl_xor_sync(~0u, ss, o);
    __shared__ float warpsum[8];
    if ((tid & 31) == 0) warpsum[tid >> 5] = ss;
    __syncthreads();
    float tot = 0.f;
#pragma unroll
    for (int i = 0; i < 8; i++) tot += warpsum[i];
    const float rs = rsqrtf(tot / (float)DIM + EPS);

    const int tv = row % VS;
    const int f  = tv / TPF;
    const int r  = tv % TPF;
    const int hh = r / NW;
    const int ww = r % NW;

    for (int p = tid; p < DIM / 2; p += 256) {
        int c = p & 63;
        int idx = (c < 22) ? f : ((c < 43) ? hh : ww);
        float ang = freqs[idx * 64 + c];
        float sn, cs;
        sincosf(ang, &sn, &cs);
        float x0 = x[2 * p]     * rs * w[2 * p];
        float x1 = x[2 * p + 1] * rs * w[2 * p + 1];
        float r0 = x0 * cs - x1 * sn;
        float r1 = x0 * sn + x1 * cs;
        uint32_t h = packbf(r0, r1);
        __nv_bfloat162 H = *(__nv_bfloat162*)&h;
        uint32_t l = packbf(r0 - __bfloat162float(H.x), r1 - __bfloat162float(H.y));
        *(uint32_t*)(OH + (size_t)row * DIM + 2 * p) = h;
        *(uint32_t*)(OL + (size_t)row * DIM + 2 * p) = l;
    }
}

// ======================= mma.sync flash attention =======================
// 128 queries x 1 head per block, 8 warps (m16 each), 32-key tiles.
// Union keyset: same-view (56 tiles) + other-view same-frame tail (14 per frame;
// blocks spanning 2 frames load both tails, warps skip the wrong-frame tiles).
#define AQB  128
#define ASTR 136
#define AQR  (AQB * ASTR)          // Q array (elems)
#define ATL  (32 * ASTR)           // one K/V tile (elems)
#define ASTAGE (4 * ATL)           // Kh,Kl,Vh,Vl
#define ATT_SMEM_BYTES ((2 * AQR + 2 * ASTAGE) * 2)

__global__ __launch_bounds__(256)
void attn_mma(const __nv_bfloat16* __restrict__ Qh, const __nv_bfloat16* __restrict__ Ql,
              const __nv_bfloat16* __restrict__ Kh, const __nv_bfloat16* __restrict__ Kl,
              const __nv_bfloat16* __restrict__ Vh, const __nv_bfloat16* __restrict__ Vl,
              __nv_bfloat16* __restrict__ Oh, __nv_bfloat16* __restrict__ Ol) {
    extern __shared__ __nv_bfloat16 smb[];
    const uint32_t sbase = s2u(smb);
    const int head = blockIdx.y;
    const int q0   = blockIdx.x * AQB;
    const int v    = q0 / VS;
    const int col0 = head * HD;
    const int tid  = threadIdx.x;
    const int warp = tid >> 5, lane = tid & 31;

    const int f_lo = (q0 % VS) / TPF;
    const int f_hi = ((q0 + AQB - 1) % VS) / TPF;
    const int span = (f_hi != f_lo);
    const int fw   = ((q0 + warp * 16) % VS) / TPF;   // warp-uniform frame

    // ---- load Q tiles (hi/lo) into smem ----
    for (int i = tid; i < AQB * 16; i += 256) {
        int r = i >> 4, seg = i & 15;
        *(uint4*)&smb[r * ASTR + seg * 8] =
            *(const uint4*)&Qh[(size_t)(q0 + r) * DIM + col0 + seg * 8];
        *(uint4*)&smb[AQR + r * ASTR + seg * 8] =
            *(const uint4*)&Ql[(size_t)(q0 + r) * DIM + col0 + seg * 8];
    }

    const int baseA = v * VS;
    const int baseBv = (1 - v) * VS;
    const int NT = 56 + (span ? 28 : 14);

    const __nv_bfloat16* ptrs[4] = {Kh, Kl, Vh, Vl};

    auto tile_base = [&](int t) -> int {
        if (t < 56) return baseA + t * 32;
        int tt = t - 56;
        int fi = (tt < 14) ? f_lo : f_hi;
        int ttt = (tt < 14) ? tt : tt - 14;
        return baseBv + fi * TPF + ttt * 32;
    };

    auto issue_tile = [&](int t, int s) {
        int kb = tile_base(t);
#pragma unroll
        for (int j = 0; j < 8; j++) {
            int i = tid + j * 256;        // 0..2047
            int arr = i >> 9;
            int idx = i & 511;
            int r = idx >> 4, seg = idx & 15;
            const __nv_bfloat16* src = ptrs[arr] + (size_t)(kb + r) * DIM + col0 + seg * 8;
            uint32_t dst = sbase + (uint32_t)(2 * AQR + s * ASTAGE + arr * ATL + r * ASTR + seg * 8) * 2;
            cp16(dst, src);
        }
        cp_commit();
    };

    issue_tile(0, 0);

    float m[2] = {-1e30f, -1e30f};
    float l[2] = {0.f, 0.f};
    float acc[16][4];
#pragma unroll
    for (int nt = 0; nt < 16; nt++)
#pragma unroll
        for (int j = 0; j < 4; j++) acc[nt][j] = 0.f;

    const uint32_t q_aoff = (uint32_t)(warp * 16 + (lane & 15)) * (ASTR * 2)
                          + (uint32_t)((lane >> 4) * 16);
    const uint32_t k_bro  = (uint32_t)((lane & 7) + 8 * ((lane >> 4) & 1));
    const uint32_t k_bco  = (uint32_t)(((lane >> 3) & 1) * 16);
    const uint32_t v_row  = (uint32_t)(lane & 15);
    const uint32_t v_cofs = (uint32_t)(8 * ((lane >> 4) & 1));
    __syncthreads();

    for (int t = 0; t < NT; t++) {
        if (t + 1 < NT) { issue_tile(t + 1, (t + 1) & 1); cp_wait<1>(); }
        else            { cp_wait<0>(); }
        __syncthreads();

        // warp-uniform activity test: tail tiles only for matching frame
        bool act = (t < 56) || (((t - 56) < 14 ? f_lo : f_hi) == fw);

        if (act) {
            const uint32_t st = sbase + (uint32_t)(2 * AQR + (t & 1) * ASTAGE) * 2;
            const uint32_t khb = st, klb = st + ATL * 2, vhb = st + 2 * ATL * 2, vlb = st + 3 * ATL * 2;

            float S[4][4];
#pragma unroll
            for (int nt = 0; nt < 4; nt++)
#pragma unroll
                for (int j = 0; j < 4; j++) S[nt][j] = 0.f;

#pragma unroll
            for (int ks = 0; ks < 8; ks++) {
                uint32_t aQh[4], aQl[4], bKh[8], bKl[8];
                ldsm_x4(aQh, sbase + q_aoff + ks * 32);
                ldsm_x4(aQl, sbase + AQR * 2 + q_aoff + ks * 32);
#pragma unroll
                for (int p = 0; p < 2; p++) {
                    uint32_t boff = (uint32_t)(p * 16 + k_bro) * (ASTR * 2) + ks * 32 + k_bco;
                    ldsm_x4(&bKh[4 * p], khb + boff);
                    ldsm_x4(&bKl[4 * p], klb + boff);
                }
#pragma unroll
                for (int nt = 0; nt < 4; nt++) {
                    mma16816(S[nt], aQh, &bKh[2 * nt]);
                    mma16816(S[nt], aQh, &bKl[2 * nt]);
                    mma16816(S[nt], aQl, &bKh[2 * nt]);
                }
            }

#pragma unroll
            for (int nt = 0; nt < 4; nt++)
#pragma unroll
                for (int j = 0; j < 4; j++) S[nt][j] *= SCALE;

            uint32_t ph[4][2], pl[4][2];
#pragma unroll
            for (int j = 0; j < 2; j++) {
                float mx = -1e30f;
#pragma unroll
                for (int nt = 0; nt < 4; nt++)
                    mx = fmaxf(mx, fmaxf(S[nt][2 * j], S[nt][2 * j + 1]));
                mx = fmaxf(mx, __shfl_xor_sync(~0u, mx, 1));
                mx = fmaxf(mx, __shfl_xor_sync(~0u, mx, 2));
                float mn = fmaxf(m[j], mx);
                float corr = __expf(m[j] - mn);
                m[j] = mn;
                float rs = 0.f;
#pragma unroll
                for (int nt = 0; nt < 4; nt++) {
                    float e0 = __expf(S[nt][2 * j]     - mn);
                    float e1 = __expf(S[nt][2 * j + 1] - mn);
                    S[nt][2 * j] = e0; S[nt][2 * j + 1] = e1;
                    rs += e0 + e1;
                }
                rs += __shfl_xor_sync(~0u, rs, 1);
                rs += __shfl_xor_sync(~0u, rs, 2);
                l[j] = l[j] * corr + rs;
#pragma unroll
                for (int nt = 0; nt < 16; nt++) {
                    acc[nt][2 * j]     *= corr;
                    acc[nt][2 * j + 1] *= corr;
                }
            }
#pragma unroll
            for (int nt = 0; nt < 4; nt++) {
#pragma unroll
                for (int j = 0; j < 2; j++) {
                    float e0 = S[nt][2 * j], e1 = S[nt][2 * j + 1];
                    uint32_t h = packbf(e0, e1);
                    __nv_bfloat162 H = *(__nv_bfloat162*)&h;
                    ph[nt][j] = h;
                    pl[nt][j] = packbf(e0 - __bfloat162float(H.x), e1 - __bfloat162float(H.y));
                }
            }

#pragma unroll
            for (int ks2 = 0; ks2 < 2; ks2++) {
                uint32_t aPh[4] = {ph[2 * ks2][0], ph[2 * ks2][1], ph[2 * ks2 + 1][0], ph[2 * ks2 + 1][1]};
                uint32_t aPl[4] = {pl[2 * ks2][0], pl[2 * ks2][1], pl[2 * ks2 + 1][0], pl[2 * ks2 + 1][1]};
#pragma unroll
                for (int dp = 0; dp < 8; dp++) {
                    uint32_t bVh[4], bVl[4];
                    uint32_t voff = (uint32_t)(ks2 * 16 + v_row) * (ASTR * 2)
                                  + (uint32_t)(dp * 16 + v_cofs) * 2;
                    ldsm_x4_t(bVh, vhb + voff);
                    mma16816(acc[2 * dp],     aPh, &bVh[0]);
                    mma16816(acc[2 * dp + 1], aPh, &bVh[2]);
                    mma16816(acc[2 * dp],     aPl, &bVh[0]);
                    mma16816(acc[2 * dp + 1], aPl, &bVh[2]);
                    ldsm_x4_t(bVl, vlb + voff);
                    mma16816(acc[2 * dp],     aPh, &bVl[0]);
                    mma16816(acc[2 * dp + 1], aPh, &bVl[2]);
                }
            }
        }
        __syncthreads();
    }

    // ---- epilogue ----
#pragma unroll
    for (int j = 0; j < 2; j++) {
        float inv = 1.f / l[j];
        int row = q0 + warp * 16 + (lane >> 2) + 8 * j;
#pragma unroll
        for (int nt = 0; nt < 16; nt++) {
            float o0 = acc[nt][2 * j] * inv;
            float o1 = acc[nt][2 * j + 1] * inv;
            uint32_t h = packbf(o0, o1);
            __nv_bfloat162 H = *(__nv_bfloat162*)&h;
            uint32_t lo = packbf(o0 - __bfloat162float(H.x), o1 - __bfloat162float(H.y));
            size_t off = (size_t)row * DIM + col0 + nt * 8 + 2 * (lane & 3);
            *(uint32_t*)(Oh + off) = h;
            *(uint32_t*)(Ol + off) = lo;
        }
    }
}

// ======================= launch =======================
extern "C" void kernel_launch(void* const* d_in, const int* in_sizes, int n_in,
                              void* d_out, int out_size) {
    const float* x     = (const float*)d_in[0];
    const float* freqs = (const float*)d_in[1];
    const float* q_w   = (const float*)d_in[2];
    const float* q_b   = (const float*)d_in[3];
    const float* k_w   = (const float*)d_in[4];
    const float* k_b   = (const float*)d_in[5];
    const float* v_w   = (const float*)d_in[6];
    const float* v_b   = (const float*)d_in[7];
    const float* o_w   = (const float*)d_in[8];
    const float* o_b   = (const float*)d_in[9];
    const float* nqw   = (const float*)d_in[10];
    const float* nkw   = (const float*)d_in[11];

    float *gq, *gk;
    __nv_bfloat16 *xh, *xl, *qh, *ql, *kh, *kl, *vh, *vl, *oh, *ol, *wh, *wl;
    cudaGetSymbolAddress((void**)&gq, g_q);
    cudaGetSymbolAddress((void**)&gk, g_k);
    cudaGetSymbolAddress((void**)&xh, g_xh);
    cudaGetSymbolAddress((void**)&xl, g_xl);
    cudaGetSymbolAddress((void**)&qh, g_qh);
    cudaGetSymbolAddress((void**)&ql, g_ql);
    cudaGetSymbolAddress((void**)&kh, g_kh);
    cudaGetSymbolAddress((void**)&kl, g_kl);
    cudaGetSymbolAddress((void**)&vh, g_vh);
    cudaGetSymbolAddress((void**)&vl, g_vl);
    cudaGetSymbolAddress((void**)&oh, g_oh);
    cudaGetSymbolAddress((void**)&ol, g_ol);
    cudaGetSymbolAddress((void**)&wh, g_wh);
    cudaGetSymbolAddress((void**)&wl, g_wl);

    const size_t WSZ = (size_t)DIM * DIM;
    __nv_bfloat16 *owh = wh + 3 * WSZ, *owl = wl + 3 * WSZ;

    int nx4 = TS * DIM / 4, nw4 = DIM * DIM / 4;
    split_kernel<<<(nx4 + 255) / 256, 256>>>(x, xh, xl, nx4);
    split4_kernel<<<dim3((nw4 + 255) / 256, 4), 256>>>(q_w, k_w, v_w, o_w, wh, wl, nw4);

    cudaFuncSetAttribute(gemm_qkv, cudaFuncAttributeMaxDynamicSharedMemorySize,
                         GEMM_SMEM_BYTES);
    cudaFuncSetAttribute(gemm_o, cudaFuncAttributeMaxDynamicSharedMemorySize,
                         GEMM_SMEM_BYTES);
    gemm_qkv<<<dim3(DIM / 128, TS / 128, 3), 256, GEMM_SMEM_BYTES>>>(
        xh, xl, wh, wl, q_b, k_b, v_b, gq, gk, vh, vl);

    norm_rope_kernel<<<dim3(TS, 2), 256>>>(gq, gk, freqs, nqw, nkw, qh, ql, kh, kl);

    cudaFuncSetAttribute(attn_mma, cudaFuncAttributeMaxDynamicSharedMemorySize,
                         ATT_SMEM_BYTES);
    attn_mma<<<dim3(TS / AQB, NH), 256, ATT_SMEM_BYTES>>>(qh, ql, kh, kl, vh, vl, oh, ol);

    gemm_o<<<dim3(DIM / 128, TS / 128), 256, GEMM_SMEM_BYTES>>>(
        oh, ol, owh, owl, o_b, (float*)d_out);
}